// round 1
// baseline (speedup 1.0000x reference)
#include <cuda_runtime.h>
#include <math.h>

// ---------------- dims ----------------
#define Bsz 2
#define Tn  2048
#define Cn  1024
#define Vn  32000
#define Ln  4
#define En  3
#define Hn  4096
#define BT  (Bsz*Tn)   // 4096 tokens

// ---------------- scratch (__device__ globals; no allocs) ----------------
__device__ float g_X  [BT*Cn];
__device__ float g_HS [BT*Cn];
__device__ float g_MIX[BT*Cn];   // reused as RS (= r*state) after scan
__device__ float g_R  [BT*Cn];
__device__ float g_K  [BT*Cn];
__device__ float g_V  [BT*Cn];
__device__ float g_ST [BT*Cn];
__device__ float g_H  [BT*Cn];
__device__ float g_HZ [BT*2*Cn];
__device__ float g_HID[(size_t)BT*Hn];
__device__ float g_SC [BT];
__device__ int   g_CNT[En];
__device__ int   g_LIST[En*BT];

// ---------------- embedding gather ----------------
__global__ void embed_k(const int* __restrict__ idx, const float* __restrict__ emb) {
    int i = blockIdx.x*blockDim.x + threadIdx.x;
    if (i >= BT*Cn) return;
    int row = i >> 10, c = i & 1023;
    g_X[i] = emb[(size_t)idx[row]*Cn + c];
}

// ---------------- LayerNorm (block per row, 256 thr, C=1024) ----------------
__global__ void ln_k(const float* __restrict__ in, const float* __restrict__ g,
                     const float* __restrict__ b, float* __restrict__ out) {
    int row = blockIdx.x;
    const float* p = in + (size_t)row*Cn;
    float v[4];
    float s = 0.f, ss = 0.f;
#pragma unroll
    for (int j = 0; j < 4; j++) {
        v[j] = p[threadIdx.x + j*256];
        s  += v[j];
        ss += v[j]*v[j];
    }
#pragma unroll
    for (int o = 16; o > 0; o >>= 1) {
        s  += __shfl_xor_sync(0xffffffffu, s,  o);
        ss += __shfl_xor_sync(0xffffffffu, ss, o);
    }
    __shared__ float sh[2][8];
    int w = threadIdx.x >> 5;
    if ((threadIdx.x & 31) == 0) { sh[0][w] = s; sh[1][w] = ss; }
    __syncthreads();
    s = 0.f; ss = 0.f;
#pragma unroll
    for (int j = 0; j < 8; j++) { s += sh[0][j]; ss += sh[1][j]; }
    float mean = s * (1.f/Cn);
    float var  = ss * (1.f/Cn) - mean*mean;
    float rstd = rsqrtf(var + 1e-5f);
    float* o = out + (size_t)row*Cn;
#pragma unroll
    for (int j = 0; j < 4; j++) {
        int c = threadIdx.x + j*256;
        o[c] = (v[j]-mean)*rstd*g[c] + b[c];
    }
}

// ---------------- token-shift mix ----------------
__global__ void mix_k() {
    int i = blockIdx.x*blockDim.x + threadIdx.x;
    if (i >= BT*Cn) return;
    int t = (i >> 10) & (Tn - 1);
    float prev = t ? g_HS[i - Cn] : 0.f;
    g_MIX[i] = 0.5f*(g_HS[i] + prev);
}

// ---------------- rwkv state scan + r*state (serial over T per (b,c)) ----------------
__global__ void scan_k() {
    int lane = blockIdx.x*blockDim.x + threadIdx.x;
    if (lane >= Bsz*Cn) return;
    int b = lane >> 10, c = lane & 1023;
    size_t base = (size_t)b*Tn*Cn + c;
    float acc = 0.f;
#pragma unroll 4
    for (int t = 0; t < Tn; t++) {
        size_t id = base + (size_t)t*Cn;
        acc += g_K[id]*g_V[id];
        float st = acc / (float)(t+1);
        g_ST[id]  = st;
        g_MIX[id] = g_R[id]*st;   // RS reuse of MIX buffer
    }
}

// ---------------- routing: conf/affinity dots, argmax, compaction ----------------
__global__ void zcnt_k() { if (threadIdx.x < En) g_CNT[threadIdx.x] = 0; }

__global__ void route_k(const float* __restrict__ wc,   // [E,C] this layer
                        const float* __restrict__ wa,   // [C,E] this layer
                        const float* __restrict__ shp)  // [E]
{
    int bt = blockIdx.x;
    const float* hp = g_H + (size_t)bt*Cn;
    float p[6] = {0,0,0,0,0,0};
    for (int c = threadIdx.x; c < Cn; c += 128) {
        float hv = hp[c];
        p[0] += hv*wc[c];
        p[1] += hv*wc[Cn + c];
        p[2] += hv*wc[2*Cn + c];
        p[3] += hv*wa[c*En + 0];
        p[4] += hv*wa[c*En + 1];
        p[5] += hv*wa[c*En + 2];
    }
#pragma unroll
    for (int o = 16; o > 0; o >>= 1)
#pragma unroll
        for (int q = 0; q < 6; q++) p[q] += __shfl_xor_sync(0xffffffffu, p[q], o);
    __shared__ float sm[4][6];
    int w = threadIdx.x >> 5;
    if ((threadIdx.x & 31) == 0) {
#pragma unroll
        for (int q = 0; q < 6; q++) sm[w][q] = p[q];
    }
    __syncthreads();
    if (threadIdx.x == 0) {
        float d[6];
#pragma unroll
        for (int q = 0; q < 6; q++) d[q] = sm[0][q] + sm[1][q] + sm[2][q] + sm[3][q];
        float best = -3.4e38f, wcf = 0.f;
        int wi = 0;
#pragma unroll
        for (int e = 0; e < En; e++) {
            float conf = 1.f/(1.f + expf(-d[e]));
            float bid  = conf*shp[e] + d[3+e];
            if (bid > best) { best = bid; wi = e; wcf = conf; }  // strict > => first-max, matches argmax
        }
        g_SC[bt] = wcf / (wcf + 1e-6f);
        int pos = atomicAdd(&g_CNT[wi], 1);
        g_LIST[wi*BT + pos] = bt;
    }
}

// ---------------- hz = concat(h, state) ----------------
__global__ void hz_k() {
    int i = blockIdx.x*blockDim.x + threadIdx.x;
    if (i >= BT*2*Cn) return;
    int row = i >> 11;
    int c = i & (2*Cn - 1);
    g_HZ[i] = (c < Cn) ? g_H[(size_t)row*Cn + c] : g_ST[(size_t)row*Cn + c - Cn];
}

// ---------------- fp32 SGEMM: 128x128x16, 256 thr, 8x8/thr ----------------
// MODE 0: C=acc   1: C=sigmoid(acc)   2: C+=acc   3: C=relu(acc)
// MODE 4: scatter: tok=rows[m]; X[tok*N+n] += acc*scal[tok]
// gatherA: A row index = rows[m] (token id); cntp: dynamic M (tiles early-exit)
template<int MODE>
__global__ void __launch_bounds__(256) gemm_k(
    const float* __restrict__ A, const float* __restrict__ Bm, float* __restrict__ Cm,
    int K, int N,
    const int* __restrict__ rows, const int* __restrict__ cntp,
    const float* __restrict__ scal, int gatherA)
{
    int Meff = cntp ? *cntp : BT;
    int m0 = blockIdx.y * 128;
    if (m0 >= Meff) return;

    __shared__ float As[16][132];
    __shared__ float Bs[16][128];

    int tid = threadIdx.x;
    int am = tid >> 2;
    int ak = (tid & 3) << 2;
    int bk = tid >> 5;
    int bn = (tid & 31) << 2;
    const float* Bp = Bm + (size_t)blockIdx.x*128 + bn;

    const float* Ap[2];
#pragma unroll
    for (int i = 0; i < 2; i++) {
        int m = m0 + am + i*64;
        int mm = (m < Meff) ? m : (Meff - 1);
        int gr = gatherA ? rows[mm] : mm;
        Ap[i] = A + (size_t)gr*K + ak;
    }

    float acc[8][8];
#pragma unroll
    for (int i = 0; i < 8; i++)
#pragma unroll
        for (int j = 0; j < 8; j++) acc[i][j] = 0.f;

    int tx = tid & 15, ty = tid >> 4;

    for (int k0 = 0; k0 < K; k0 += 16) {
#pragma unroll
        for (int i = 0; i < 2; i++) {
            float4 va = *(const float4*)(Ap[i] + k0);
            As[ak+0][am + i*64] = va.x;
            As[ak+1][am + i*64] = va.y;
            As[ak+2][am + i*64] = va.z;
            As[ak+3][am + i*64] = va.w;
        }
#pragma unroll
        for (int i = 0; i < 2; i++) {
            *(float4*)&Bs[bk + i*8][bn] = *(const float4*)(Bp + (size_t)(k0 + bk + i*8)*N);
        }
        __syncthreads();
#pragma unroll
        for (int kk = 0; kk < 16; kk++) {
            float a[8], bfr[8];
            *(float4*)(a)     = *(const float4*)&As[kk][ty*8];
            *(float4*)(a + 4) = *(const float4*)&As[kk][ty*8 + 4];
            *(float4*)(bfr)     = *(const float4*)&Bs[kk][tx*8];
            *(float4*)(bfr + 4) = *(const float4*)&Bs[kk][tx*8 + 4];
#pragma unroll
            for (int i = 0; i < 8; i++)
#pragma unroll
                for (int j = 0; j < 8; j++)
                    acc[i][j] = fmaf(a[i], bfr[j], acc[i][j]);
        }
        __syncthreads();
    }

    int cn = blockIdx.x*128 + tx*8;
#pragma unroll
    for (int i = 0; i < 8; i++) {
        int m = m0 + ty*8 + i;
        if (m >= Meff) break;
        if (MODE == 4) {
            int tok = rows[m];
            float sc = scal[tok];
            float* xr = Cm + (size_t)tok*N + cn;
#pragma unroll
            for (int j = 0; j < 8; j++) xr[j] += acc[i][j]*sc;
        } else {
            float* cr = Cm + (size_t)m*N + cn;
#pragma unroll
            for (int j = 0; j < 8; j++) {
                float v = acc[i][j];
                if (MODE == 1) v = 1.f/(1.f + expf(-v));
                else if (MODE == 2) v += cr[j];
                else if (MODE == 3) v = fmaxf(v, 0.f);
                cr[j] = v;
            }
        }
    }
}

// ---------------- launch ----------------
extern "C" void kernel_launch(void* const* d_in, const int* in_sizes, int n_in,
                              void* d_out, int out_size)
{
    const int*   idx   = (const int*)  d_in[0];
    const float* shares= (const float*)d_in[1];
    const float* emb   = (const float*)d_in[2];
    const float* ln1g  = (const float*)d_in[3];
    const float* ln1b  = (const float*)d_in[4];
    const float* ln2g  = (const float*)d_in[5];
    const float* ln2b  = (const float*)d_in[6];
    const float* Wr    = (const float*)d_in[7];
    const float* Wk    = (const float*)d_in[8];
    const float* Wv    = (const float*)d_in[9];
    const float* Wo    = (const float*)d_in[10];
    const float* W1    = (const float*)d_in[11];
    const float* W2    = (const float*)d_in[12];
    const float* wconf = (const float*)d_in[13];
    const float* Wl1   = (const float*)d_in[14];
    const float* Wl2   = (const float*)d_in[15];
    // d_in[16] = W_diff (unused by forward)
    const float* Waff  = (const float*)d_in[17];
    const float* lnfg  = (const float*)d_in[18];
    const float* lnfb  = (const float*)d_in[19];
    const float* headW = (const float*)d_in[20];
    float* out = (float*)d_out;
    (void)in_sizes; (void)n_in; (void)out_size;

    float *X, *HS, *MIX, *Rb, *Kb, *Vb, *ST, *Hh, *HZ, *HID, *SC;
    int *CNT, *LIST;
    cudaGetSymbolAddress((void**)&X,   g_X);
    cudaGetSymbolAddress((void**)&HS,  g_HS);
    cudaGetSymbolAddress((void**)&MIX, g_MIX);
    cudaGetSymbolAddress((void**)&Rb,  g_R);
    cudaGetSymbolAddress((void**)&Kb,  g_K);
    cudaGetSymbolAddress((void**)&Vb,  g_V);
    cudaGetSymbolAddress((void**)&ST,  g_ST);
    cudaGetSymbolAddress((void**)&Hh,  g_H);
    cudaGetSymbolAddress((void**)&HZ,  g_HZ);
    cudaGetSymbolAddress((void**)&HID, g_HID);
    cudaGetSymbolAddress((void**)&SC,  g_SC);
    cudaGetSymbolAddress((void**)&CNT, g_CNT);
    cudaGetSymbolAddress((void**)&LIST,g_LIST);

    embed_k<<<(BT*Cn)/256, 256>>>(idx, emb);

    dim3 gC(Cn/128, BT/128);   // N=1024 outputs
    dim3 gH(Hn/128, BT/128);   // N=4096 outputs

    for (int l = 0; l < Ln; l++) {
        ln_k<<<BT, 256>>>(X, ln1g + (size_t)l*Cn, ln1b + (size_t)l*Cn, HS);
        mix_k<<<(BT*Cn)/256, 256>>>();

        gemm_k<1><<<gC, 256>>>(MIX, Wr + (size_t)l*Cn*Cn, Rb, Cn, Cn, nullptr, nullptr, nullptr, 0);
        gemm_k<0><<<gC, 256>>>(MIX, Wk + (size_t)l*Cn*Cn, Kb, Cn, Cn, nullptr, nullptr, nullptr, 0);
        gemm_k<0><<<gC, 256>>>(MIX, Wv + (size_t)l*Cn*Cn, Vb, Cn, Cn, nullptr, nullptr, nullptr, 0);

        scan_k<<<16, 128>>>();   // writes ST and RS (into MIX)

        gemm_k<2><<<gC, 256>>>(MIX, Wo + (size_t)l*Cn*Cn, X, Cn, Cn, nullptr, nullptr, nullptr, 0);

        ln_k<<<BT, 256>>>(X, ln2g + (size_t)l*Cn, ln2b + (size_t)l*Cn, Hh);

        zcnt_k<<<1, 32>>>();
        route_k<<<BT, 128>>>(wconf + (size_t)l*En*Cn, Waff + (size_t)l*Cn*En, shares + (size_t)l*En);
        hz_k<<<(BT*2*Cn)/256, 256>>>();

        for (int e = 0; e < 2; e++) {
            gemm_k<3><<<gH, 256>>>(Hh,  W1 + ((size_t)l*2 + e)*Cn*Hn, HID, Cn, Hn,
                                   LIST + e*BT, CNT + e, nullptr, 1);
            gemm_k<4><<<gC, 256>>>(HID, W2 + ((size_t)l*2 + e)*Hn*Cn, X,   Hn, Cn,
                                   LIST + e*BT, CNT + e, SC, 0);
        }
        gemm_k<3><<<gH, 256>>>(HZ,  Wl1 + (size_t)l*2*Cn*Hn, HID, 2*Cn, Hn,
                               LIST + 2*BT, CNT + 2, nullptr, 1);
        gemm_k<4><<<gC, 256>>>(HID, Wl2 + (size_t)l*Hn*Cn,   X,   Hn,   Cn,
                               LIST + 2*BT, CNT + 2, SC, 0);
    }

    ln_k<<<BT, 256>>>(X, lnfg, lnfb, Hh);
    gemm_k<0><<<dim3(Vn/128, BT/128), 256>>>(Hh, headW, out, Cn, Vn, nullptr, nullptr, nullptr, 0);
}